// round 12
// baseline (speedup 1.0000x reference)
#include <cuda_runtime.h>
#include <cuda_bf16.h>

// exp[b,q] = sum_j (-1)^{bit_{9-q}(j)} * (re[b,j]^2 + im[b,j]^2)
// BATCH=8192, STATE_DIM=1024, NQ=10. pauli_z_obs ignored (every Z_q is
// diagonal with +-1 entries; the dense 80MB observable tensor is never read).
//
// FINAL kernel (best measured: 10.56us = 6.07 TB/s served, ~95% of the
// streaming floor): one warp per row; 128-thread CTAs, grid=2048,
// __launch_bounds__(128,14) -> 32 regs, 14 CTAs/SM, single wave.
// Per warp: 4 passes of 4 front-batched LDG.128 (lane-coalesced).
//
//   element bits 0,1 -> qubits 9,8  (register fold)
//   chunk   bits 0..2-> qubits 2,1,0 (register signed accumulate)
//   lane    bits 0..4-> qubits 7..3 (growing Walsh butterfly, 40 SHFL/row)
//
// Output: after the butterfly all accumulators are lane-uniform; lanes 0..9
// each select acc[lane] and the warp issues ONE coalesced predicated 40B
// STG.32 (this removed the lane-0 serialized store tail and produced the
// best measurement).
//
// Convergence evidence across rounds: occupancy 37-77%, MLP 4-8, 2-vs-4
// latency walls, cache hints, CTA granularity all measured within +-1 timer
// tick (224ns) of each other; only the store-shape fix moved the needle.
// The memory system is the pacing resource at ~95% of its ceiling.

#define STATE_DIM 1024
#define NQ 10

__global__ __launch_bounds__(128, 14)
void qmeas_kernel(const float4* __restrict__ re4,
                  const float4* __restrict__ im4,
                  float* __restrict__ out)
{
    const int lane = threadIdx.x & 31;
    const int warp = threadIdx.x >> 5;
    const unsigned row = blockIdx.x * 4u + warp;           // 0..8191
    const unsigned base = row * (STATE_DIM / 4) + lane;    // float4 index
    const float4* __restrict__ rb = re4 + base;
    const float4* __restrict__ ib = im4 + base;

    float s = 0.f, a9 = 0.f, a8 = 0.f, a0 = 0.f, a1 = 0.f, a2 = 0.f;

    #pragma unroll
    for (int pass = 0; pass < 4; pass++) {
        const float4* __restrict__ p = (pass < 2) ? rb : ib;
        const int cb = (pass & 1) * 4;

        // Front-batched: 4 x LDG.128, lane-coalesced (512B per warp-instr).
        float4 v[4];
        #pragma unroll
        for (int k = 0; k < 4; k++)
            v[k] = p[32 * (cb + k)];

        #pragma unroll
        for (int k = 0; k < 4; k++) {
            const int c = cb + k;
            const float p0 = v[k].x * v[k].x;
            const float p1 = v[k].y * v[k].y;
            const float p2 = v[k].z * v[k].z;
            const float p3 = v[k].w * v[k].w;

            const float q01 = p0 + p1, q23 = p2 + p3;
            a9 += (p0 - p1) + (p2 - p3);     // elem bit0 -> qubit9
            a8 += q01 - q23;                 // elem bit1 -> qubit8
            const float sc = q01 + q23;
            s  += sc;
            a2 += (c & 1) ? -sc : sc;        // chunk bit0 -> j bit7 -> qubit2
            a1 += (c & 2) ? -sc : sc;        // chunk bit1 -> j bit8 -> qubit1
            a0 += (c & 4) ? -sc : sc;        // chunk bit2 -> j bit9 -> qubit0
        }
    }

    float acc[NQ];
    acc[0] = a0; acc[1] = a1; acc[2] = a2; acc[8] = a8; acc[9] = a9;

    // Growing Walsh butterfly over 5 lane bits. Lane bit k -> j bit 2+k
    // -> qubit 7-k.
    #pragma unroll
    for (int k = 0; k < 5; k++) {
        const int off = 1 << k;
        acc[0] += __shfl_xor_sync(0xffffffffu, acc[0], off);
        acc[1] += __shfl_xor_sync(0xffffffffu, acc[1], off);
        acc[2] += __shfl_xor_sync(0xffffffffu, acc[2], off);
        acc[8] += __shfl_xor_sync(0xffffffffu, acc[8], off);
        acc[9] += __shfl_xor_sync(0xffffffffu, acc[9], off);
        #pragma unroll
        for (int q = 8 - k; q <= 7; q++)     // accumulators created so far
            acc[q] += __shfl_xor_sync(0xffffffffu, acc[q], off);

        const float sp = __shfl_xor_sync(0xffffffffu, s, off);
        const float d  = s - sp;
        const unsigned sgn = ((unsigned)(lane & off)) << (31 - k);
        acc[7 - k] = __int_as_float(__float_as_int(d) ^ sgn);
        s += sp;
    }

    // acc[0..9] are lane-uniform. Each of lanes 0..9 selects its own qubit's
    // value (uniform-register select chain, off the memory path) and the warp
    // issues ONE coalesced 40B STG.32.
    float myval = acc[0];
    #pragma unroll
    for (int q = 1; q < NQ; q++)
        if (lane == q) myval = acc[q];

    if (lane < NQ)
        out[row * NQ + lane] = myval;
}

extern "C" void kernel_launch(void* const* d_in, const int* in_sizes, int n_in,
                              void* d_out, int out_size)
{
    const float4* state_real = (const float4*)d_in[0];
    const float4* state_imag = (const float4*)d_in[1];
    // d_in[2] = pauli_z_obs (ignored)

    const int batch = in_sizes[0] / STATE_DIM;   // 8192
    float* out = (float*)d_out;

    // 2048 CTAs x 128 threads; one warp per row.
    qmeas_kernel<<<batch / 4, 128>>>(state_real, state_imag, out);
}

// round 14
// speedup vs baseline: 1.0275x; 1.0275x over previous
#include <cuda_runtime.h>
#include <cuda_bf16.h>

// exp[b,q] = sum_j (-1)^{bit_{9-q}(j)} * (re[b,j]^2 + im[b,j]^2)
// BATCH=8192, STATE_DIM=1024, NQ=10. pauli_z_obs ignored (every Z_q is
// diagonal with +-1 entries; the dense 80MB observable tensor is never read).
//
// FINAL kernel (best measured: 10.56us = 6.07 TB/s served, ~95% of the LTS
// streaming ceiling): one warp per row; 128-thread CTAs, grid=2048,
// __launch_bounds__(128,14) -> 32 regs, 14 CTAs/SM, single wave.
// Per warp: 4 passes of 4 front-batched LDG.128 (lane-coalesced, 512B per
// warp instruction).
//
//   element bits 0,1 -> qubits 9,8  (register fold)
//   chunk   bits 0..2-> qubits 2,1,0 (register signed accumulate)
//   lane    bits 0..4-> qubits 7..3 (growing Walsh butterfly, 40 SHFL/row)
//
// Output: after the butterfly all accumulators are lane-uniform; lanes 0..9
// each select acc[lane] and the warp issues ONE coalesced predicated 40B
// STG.32 (removing the lane-0 serialized store tail — the only change since
// R6 that measured above the +-224ns noise floor).
//
// Convergence evidence: occupancy 37-77%, MLP 4-8, 2-vs-4 latency walls,
// cache hints, CTA granularity, fmaf fusion all measured within +-1 timer
// tick. The memory system paces the kernel at ~95% of its ceiling; SM-side
// pipes idle (fma 13%, alu 2%, issue 26%). This source is locked as final.

#define STATE_DIM 1024
#define NQ 10

__global__ __launch_bounds__(128, 14)
void qmeas_kernel(const float4* __restrict__ re4,
                  const float4* __restrict__ im4,
                  float* __restrict__ out)
{
    const int lane = threadIdx.x & 31;
    const int warp = threadIdx.x >> 5;
    const unsigned row = blockIdx.x * 4u + warp;           // 0..8191
    const unsigned base = row * (STATE_DIM / 4) + lane;    // float4 index
    const float4* __restrict__ rb = re4 + base;
    const float4* __restrict__ ib = im4 + base;

    float s = 0.f, a9 = 0.f, a8 = 0.f, a0 = 0.f, a1 = 0.f, a2 = 0.f;

    #pragma unroll
    for (int pass = 0; pass < 4; pass++) {
        const float4* __restrict__ p = (pass < 2) ? rb : ib;
        const int cb = (pass & 1) * 4;

        // Front-batched: 4 x LDG.128, lane-coalesced (512B per warp-instr).
        float4 v[4];
        #pragma unroll
        for (int k = 0; k < 4; k++)
            v[k] = p[32 * (cb + k)];

        #pragma unroll
        for (int k = 0; k < 4; k++) {
            const int c = cb + k;
            const float p0 = v[k].x * v[k].x;
            const float p1 = v[k].y * v[k].y;
            const float p2 = v[k].z * v[k].z;
            const float p3 = v[k].w * v[k].w;

            const float q01 = p0 + p1, q23 = p2 + p3;
            a9 += (p0 - p1) + (p2 - p3);     // elem bit0 -> qubit9
            a8 += q01 - q23;                 // elem bit1 -> qubit8
            const float sc = q01 + q23;
            s  += sc;
            a2 += (c & 1) ? -sc : sc;        // chunk bit0 -> j bit7 -> qubit2
            a1 += (c & 2) ? -sc : sc;        // chunk bit1 -> j bit8 -> qubit1
            a0 += (c & 4) ? -sc : sc;        // chunk bit2 -> j bit9 -> qubit0
        }
    }

    float acc[NQ];
    acc[0] = a0; acc[1] = a1; acc[2] = a2; acc[8] = a8; acc[9] = a9;

    // Growing Walsh butterfly over 5 lane bits. Lane bit k -> j bit 2+k
    // -> qubit 7-k.
    #pragma unroll
    for (int k = 0; k < 5; k++) {
        const int off = 1 << k;
        acc[0] += __shfl_xor_sync(0xffffffffu, acc[0], off);
        acc[1] += __shfl_xor_sync(0xffffffffu, acc[1], off);
        acc[2] += __shfl_xor_sync(0xffffffffu, acc[2], off);
        acc[8] += __shfl_xor_sync(0xffffffffu, acc[8], off);
        acc[9] += __shfl_xor_sync(0xffffffffu, acc[9], off);
        #pragma unroll
        for (int q = 8 - k; q <= 7; q++)     // accumulators created so far
            acc[q] += __shfl_xor_sync(0xffffffffu, acc[q], off);

        const float sp = __shfl_xor_sync(0xffffffffu, s, off);
        const float d  = s - sp;
        const unsigned sgn = ((unsigned)(lane & off)) << (31 - k);
        acc[7 - k] = __int_as_float(__float_as_int(d) ^ sgn);
        s += sp;
    }

    // acc[0..9] are lane-uniform. Each of lanes 0..9 selects its own qubit's
    // value (uniform-register select chain, off the memory path) and the warp
    // issues ONE coalesced 40B STG.32.
    float myval = acc[0];
    #pragma unroll
    for (int q = 1; q < NQ; q++)
        if (lane == q) myval = acc[q];

    if (lane < NQ)
        out[row * NQ + lane] = myval;
}

extern "C" void kernel_launch(void* const* d_in, const int* in_sizes, int n_in,
                              void* d_out, int out_size)
{
    const float4* state_real = (const float4*)d_in[0];
    const float4* state_imag = (const float4*)d_in[1];
    // d_in[2] = pauli_z_obs (ignored)

    const int batch = in_sizes[0] / STATE_DIM;   // 8192
    float* out = (float*)d_out;

    // 2048 CTAs x 128 threads; one warp per row.
    qmeas_kernel<<<batch / 4, 128>>>(state_real, state_imag, out);
}